// round 12
// baseline (speedup 1.0000x reference)
#include <cuda_runtime.h>

// ---------------------------------------------------------------------------
// Problem constants
// ---------------------------------------------------------------------------
#define H    156
#define HP   164           // padded row: 164 % 32 == 4 -> conflict-free LDS.128
#define BSZ  4096
#define TT   128
#define NB   32            // samples per block
#define TPB  512           // 16 warps, 4/SMSP; 128-reg cap (no spill ceiling games)
#define NBHP (NB * HP)     // 5248 floats
#define OUT_O 12
#define HD4  (H / 4)       // 39

#define OUT_SZ  ((size_t)BSZ * H * OUT_O)        // 7,667,712
#define OFF_H   (OUT_SZ)
#define OFF_C   (OFF_H + 2ULL * BSZ * H)

typedef unsigned long long u64;

// scratch for layer-1 ht time series: [B][T][H]  (t*156+h flat per sample)
__device__ float g_ys[(size_t)BSZ * TT * H];

__device__ __forceinline__ float sigm(float x) {
    return __fdividef(1.0f, 1.0f + __expf(-x));
}

// packed f32x2 FMA: d.lo += a.lo*b.lo ; d.hi += a.hi*b.hi  (sm_100+ PTX only)
__device__ __forceinline__ void ffma2(u64& d, const u64 a, const u64 b) {
    asm("fma.rn.f32x2 %0, %1, %2, %0;" : "+l"(d) : "l"(a), "l"(b));
}
__device__ __forceinline__ float hsum2(u64 v) {
    float lo, hi;
    asm("mov.b64 {%0,%1}, %2;" : "=f"(lo), "=f"(hi) : "l"(v));
    return lo + hi;
}

// ---------------------------------------------------------------------------
// Fused kernel: persistent LSTM+GCN recurrence + output projection epilogue.
// 128 blocks x 512 threads (16 warps).
//   GCN:   2-row pairs q = w + 16*m (q < 78): state chunks feed both rows.
//   Gates: 1 row r = w + 16*m (8 weight streams, 4 accums -> no spills).
//
// SMEM layout (floats):
//   sX  [NBHP]        x_t transposed [n][HP]
//   sC  [2*NBHP]      cell state per layer, [n][HP]
//   sH  [2*2*NBHP]    hidden state per layer, ping-pong by t-parity
//   tC  [NBHP]        GCN relu intermediate (c)
//   tH  [NBHP]        GCN relu intermediate (h)
// total = 9*NBHP floats = 188,928 bytes (epilogue reuses the same arena)
// ---------------------------------------------------------------------------
__global__ void __launch_bounds__(TPB, 1) lstm_gcn_fused_kernel(
    const float* __restrict__ x,   const float* __restrict__ adj,
    const float* __restrict__ Wix, const float* __restrict__ bix,
    const float* __restrict__ Wih, const float* __restrict__ bih,
    const float* __restrict__ Wfx, const float* __restrict__ bfx,
    const float* __restrict__ Wfh, const float* __restrict__ bfh,
    const float* __restrict__ Wcx, const float* __restrict__ bcx,
    const float* __restrict__ Wch, const float* __restrict__ bch,
    const float* __restrict__ Wox, const float* __restrict__ boxb,
    const float* __restrict__ Woh, const float* __restrict__ boh,
    const float* __restrict__ gw1, const float* __restrict__ gw2,
    const float* __restrict__ Wout, const float* __restrict__ bout,
    float* __restrict__ dout)
{
    extern __shared__ float sm[];
    float* sX = sm;
    float* sC = sX + NBHP;
    float* sH = sC + 2 * NBHP;
    float* tC = sH + 4 * NBHP;
    float* tH = tC + NBHP;

    const int tid = threadIdx.x;
    const int w   = tid >> 5;      // warp id 0..15
    const int n   = tid & 31;      // lane = sample within tile
    const int b0  = blockIdx.x * NB;
    const int QROWS = (w < 14) ? 5 : 4;    // GCN pairs: q = w + 16m < 78
    const int GROWS = (w < 12) ? 10 : 9;   // gate rows: r = w + 16m < 156

    // zero c and h states (sC..sH contiguous: 6*NBHP; NBHP%4==0)
    for (int i = tid; i < 6 * NBHP / 4; i += TPB)
        ((float4*)sC)[i] = make_float4(0.f, 0.f, 0.f, 0.f);
    __syncthreads();

    for (int t = 0; t < TT; ++t) {
        // ---- load x_t tile transposed [n][h], vectorized (H = 39*4) ----
        for (int i = tid; i < NB * HD4; i += TPB) {
            int nn = i / HD4, kk = i - nn * HD4;
            float4 v = ((const float4*)(x + ((size_t)(b0 + nn) * TT + t) * H))[kk];
            ((float4*)(sX + nn * HP))[kk] = v;
        }
        __syncthreads();

        const int p = t & 1;
        for (int j = 0; j < 2; ++j) {
            float* cbuf = sC + j * NBHP;
            float* hR   = sH + (j * 2 + p) * NBHP;        // read (post-GCN) hidden
            float* hW   = sH + (j * 2 + (1 - p)) * NBHP;  // write ht here

            if (t > 0) {
                const float g1 = gw1[j], g2 = gw2[j];
                // ---- GCN phase A: tmp = relu(g1 * adj @ state), 2-row pairs ----
                for (int m = 0; m < QROWS; ++m) {
                    const int q = w + 16 * m;
                    const int r0 = 2 * q;
                    const ulonglong2* a0  = (const ulonglong2*)(adj + r0 * H);
                    const ulonglong2* a1  = (const ulonglong2*)(adj + (r0 + 1) * H);
                    const ulonglong2* cc  = (const ulonglong2*)(cbuf + n * HP);
                    const ulonglong2* hh2 = (const ulonglong2*)(hR + n * HP);
                    u64 ac0 = 0, ac1 = 0, ah0 = 0, ah1 = 0;
                    #pragma unroll 13
                    for (int kk = 0; kk < HD4; ++kk) {
                        ulonglong2 c4 = cc[kk];
                        ulonglong2 h4 = hh2[kk];
                        ulonglong2 w0 = a0[kk];
                        ulonglong2 w1 = a1[kk];
                        ffma2(ac0, w0.x, c4.x); ffma2(ac0, w0.y, c4.y);
                        ffma2(ah0, w0.x, h4.x); ffma2(ah0, w0.y, h4.y);
                        ffma2(ac1, w1.x, c4.x); ffma2(ac1, w1.y, c4.y);
                        ffma2(ah1, w1.x, h4.x); ffma2(ah1, w1.y, h4.y);
                    }
                    tC[n * HP + r0]     = fmaxf(g1 * hsum2(ac0), 0.0f);
                    tH[n * HP + r0]     = fmaxf(g1 * hsum2(ah0), 0.0f);
                    tC[n * HP + r0 + 1] = fmaxf(g1 * hsum2(ac1), 0.0f);
                    tH[n * HP + r0 + 1] = fmaxf(g1 * hsum2(ah1), 0.0f);
                }
                __syncthreads();
                // ---- GCN phase B: state = sigmoid(g2 * adj @ tmp) ----
                for (int m = 0; m < QROWS; ++m) {
                    const int q = w + 16 * m;
                    const int r0 = 2 * q;
                    const ulonglong2* a0  = (const ulonglong2*)(adj + r0 * H);
                    const ulonglong2* a1  = (const ulonglong2*)(adj + (r0 + 1) * H);
                    const ulonglong2* cc  = (const ulonglong2*)(tC + n * HP);
                    const ulonglong2* hh2 = (const ulonglong2*)(tH + n * HP);
                    u64 ac0 = 0, ac1 = 0, ah0 = 0, ah1 = 0;
                    #pragma unroll 13
                    for (int kk = 0; kk < HD4; ++kk) {
                        ulonglong2 c4 = cc[kk];
                        ulonglong2 h4 = hh2[kk];
                        ulonglong2 w0 = a0[kk];
                        ulonglong2 w1 = a1[kk];
                        ffma2(ac0, w0.x, c4.x); ffma2(ac0, w0.y, c4.y);
                        ffma2(ah0, w0.x, h4.x); ffma2(ah0, w0.y, h4.y);
                        ffma2(ac1, w1.x, c4.x); ffma2(ac1, w1.y, c4.y);
                        ffma2(ah1, w1.x, h4.x); ffma2(ah1, w1.y, h4.y);
                    }
                    cbuf[n * HP + r0]     = sigm(g2 * hsum2(ac0));
                    hR[n * HP + r0]       = sigm(g2 * hsum2(ah0));
                    cbuf[n * HP + r0 + 1] = sigm(g2 * hsum2(ac1));
                    hR[n * HP + r0 + 1]   = sigm(g2 * hsum2(ah1));
                }
                __syncthreads();
            }

            // ---- gate phase: 1 row, 8 weight streams, 4 accumulators ----
            for (int m = 0; m < GROWS; ++m) {
                const int r = w + 16 * m;
                const int jr = j * H + r;
                const size_t roff = (size_t)jr * H;
                const ulonglong2* wix2 = (const ulonglong2*)(Wix + roff);
                const ulonglong2* wih2 = (const ulonglong2*)(Wih + roff);
                const ulonglong2* wfx2 = (const ulonglong2*)(Wfx + roff);
                const ulonglong2* wfh2 = (const ulonglong2*)(Wfh + roff);
                const ulonglong2* wcx2 = (const ulonglong2*)(Wcx + roff);
                const ulonglong2* wch2 = (const ulonglong2*)(Wch + roff);
                const ulonglong2* wox2 = (const ulonglong2*)(Wox + roff);
                const ulonglong2* woh2 = (const ulonglong2*)(Woh + roff);
                const ulonglong2* xv2  = (const ulonglong2*)(sX + n * HP);
                const ulonglong2* hv2  = (const ulonglong2*)(hR + n * HP);

                u64 Ai = 0, Af = 0, Ag = 0, Ao = 0;

                #pragma unroll 13
                for (int kk = 0; kk < HD4; ++kk) {
                    ulonglong2 xv = xv2[kk];
                    ulonglong2 hv = hv2[kk];
                    ulonglong2 qix = wix2[kk];
                    ffma2(Ai, qix.x, xv.x); ffma2(Ai, qix.y, xv.y);
                    ulonglong2 qih = wih2[kk];
                    ffma2(Ai, qih.x, hv.x); ffma2(Ai, qih.y, hv.y);
                    ulonglong2 qfx = wfx2[kk];
                    ffma2(Af, qfx.x, xv.x); ffma2(Af, qfx.y, xv.y);
                    ulonglong2 qfh = wfh2[kk];
                    ffma2(Af, qfh.x, hv.x); ffma2(Af, qfh.y, hv.y);
                    ulonglong2 qcx = wcx2[kk];
                    ffma2(Ag, qcx.x, xv.x); ffma2(Ag, qcx.y, xv.y);
                    ulonglong2 qch = wch2[kk];
                    ffma2(Ag, qch.x, hv.x); ffma2(Ag, qch.y, hv.y);
                    ulonglong2 qox = wox2[kk];
                    ffma2(Ao, qox.x, xv.x); ffma2(Ao, qox.y, xv.y);
                    ulonglong2 qoh = woh2[kk];
                    ffma2(Ao, qoh.x, hv.x); ffma2(Ao, qoh.y, hv.y);
                }

                const float ai = bix[jr] + bih[jr] + hsum2(Ai);
                const float af = bfx[jr] + bfh[jr] + hsum2(Af);
                const float ag = bcx[jr] + bch[jr] + hsum2(Ag);
                const float ao = boxb[jr] + boh[jr] + hsum2(Ao);

                const float it = sigm(ai);
                const float ft = sigm(af);
                const float ot = sigm(ao);
                const float cand = tanhf(ag);
                const float cp = cbuf[n * HP + r];
                const float ct = ft * cp + it * cand;
                const float ht = ot * tanhf(ct);
                cbuf[n * HP + r] = ct;
                hW[n * HP + r]   = ht;
            }
            __syncthreads();
        }

        // ---- dump layer-1 ht to ys scratch, vectorized ----
        const float* h1 = sH + (1 * 2 + (1 - p)) * NBHP;
        for (int i = tid; i < NB * HD4; i += TPB) {
            int nn = i / HD4, kk = i - nn * HD4;
            float4 v = ((const float4*)(h1 + nn * HP))[kk];
            ((float4*)(g_ys + ((size_t)(b0 + nn) * TT + t) * H))[kk] = v;
        }
        __syncthreads();
    }

    // ---- final h_n / c_n (final h is in parity buffer 0 after t=127) ----
    for (int i = tid; i < 2 * NB * H; i += TPB) {
        int j = i / (NB * H);
        int rem = i - j * NB * H;
        int nn = rem / H, hh = rem - nn * H;
        size_t gi = ((size_t)j * BSZ + b0 + nn) * H + hh;
        dout[OFF_H + gi] = sH[(j * 2 + 0) * NBHP + nn * HP + hh];
        dout[OFF_C + gi] = sC[j * NBHP + nn * HP + hh];
    }
    __syncthreads();

    // ---- projection epilogue (reuses SMEM arena; states are dead now) ----
    // Per sample s: buf[19968] = ys flat (t*156+h), viewed [156][128];
    //   out[b][f*12+o] = b_out[o] + sum_t2 buf[f*128+t2] * W_out[o][t2]
    float* sWt  = sm;                 // transposed: [t2][12]
    float* sBuf = sm + TT * OUT_O;    // 19968 floats

    for (int i = tid; i < OUT_O * TT; i += TPB) {
        int o = i / TT, t2 = i - o * TT;
        sWt[t2 * OUT_O + o] = Wout[i];
    }
    for (int s = 0; s < NB; ++s) {
        __syncthreads();   // protect sBuf overwrite vs previous reads (and sWt 1st pass)
        const float4* src4 = (const float4*)(g_ys + (size_t)(b0 + s) * (TT * H));
        for (int i = tid; i < (TT * H) / 4; i += TPB)
            ((float4*)sBuf)[i] = src4[i];
        __syncthreads();
        for (int idx = tid; idx < H * OUT_O; idx += TPB) {
            int f = idx / OUT_O, o = idx - f * OUT_O;
            float acc = bout[o];
            const float* bf = sBuf + f * TT;
            #pragma unroll 8
            for (int t2 = 0; t2 < TT; ++t2)
                acc += bf[t2] * sWt[t2 * OUT_O + o];
            dout[(size_t)(b0 + s) * (H * OUT_O) + idx] = acc;
        }
    }
}

// ---------------------------------------------------------------------------
extern "C" void kernel_launch(void* const* d_in, const int* in_sizes, int n_in,
                              void* d_out, int out_size)
{
    const float* x    = (const float*)d_in[0];
    const float* adj  = (const float*)d_in[1];
    const float* Wix  = (const float*)d_in[2];
    const float* bix  = (const float*)d_in[3];
    const float* Wih  = (const float*)d_in[4];
    const float* bih  = (const float*)d_in[5];
    const float* Wfx  = (const float*)d_in[6];
    const float* bfx  = (const float*)d_in[7];
    const float* Wfh  = (const float*)d_in[8];
    const float* bfh  = (const float*)d_in[9];
    const float* Wcx  = (const float*)d_in[10];
    const float* bcx  = (const float*)d_in[11];
    const float* Wch  = (const float*)d_in[12];
    const float* bch  = (const float*)d_in[13];
    const float* Wox  = (const float*)d_in[14];
    const float* boxb = (const float*)d_in[15];
    const float* Woh  = (const float*)d_in[16];
    const float* boh  = (const float*)d_in[17];
    const float* gw1  = (const float*)d_in[18];
    const float* gw2  = (const float*)d_in[19];
    const float* Wout = (const float*)d_in[20];
    const float* bout = (const float*)d_in[21];
    float* out = (float*)d_out;

    const int smem1 = 9 * NBHP * (int)sizeof(float);   // 188,928 B
    cudaFuncSetAttribute(lstm_gcn_fused_kernel,
                         cudaFuncAttributeMaxDynamicSharedMemorySize, smem1);

    lstm_gcn_fused_kernel<<<BSZ / NB, TPB, smem1>>>(
        x, adj, Wix, bix, Wih, bih, Wfx, bfx, Wfh, bfh,
        Wcx, bcx, Wch, bch, Wox, boxb, Woh, boh, gw1, gw2,
        Wout, bout, out);
}